// round 5
// baseline (speedup 1.0000x reference)
#include <cuda_runtime.h>
#include <cuda_bf16.h>
#include <cstdint>
#include <cstddef>

// Problem dims (fixed by the dataset)
#define SEQ_L 2048
#define BATCH 8
#define DIM   2048
#define M_ROWS (SEQ_L * BATCH)   // 16384
#define K_DIM  DIM               // 2048
#define N_DIM  DIM               // 2048

// GEMM tiling (int8): CTA 128x128, warp tile 64x32, KT=64 (one 64B row chunk)
#define MT 128
#define NT 128
#define KT 64
#define NCHUNK (K_DIM / KT)      // 32
#define ROWB 80                  // 64B data + 16B pad (conflict-free ldmatrix)

#define OFF_AHI 0
#define OFF_ALO (128 * ROWB)         // 10240
#define OFF_BHI (2 * 128 * ROWB)     // 20480
#define OFF_BLO (3 * 128 * ROWB)     // 30720
#define STAGE   (4 * 128 * ROWB)     // 40960
#define SMEM_TOTAL (2 * STAGE)       // 81920

// Scratch (device globals — allocation-free rule)
__device__ float  g_xmix[(size_t)M_ROWS * K_DIM];   // fp32 x_mix
__device__ int8_t g_xqh[(size_t)M_ROWS * K_DIM];
__device__ int8_t g_xql[(size_t)M_ROWS * K_DIM];
__device__ int8_t g_wqh[(size_t)N_DIM * K_DIM];
__device__ int8_t g_wql[(size_t)N_DIM * K_DIM];
__device__ float  g_sx[M_ROWS];
__device__ float  g_sw[N_DIM];

// ---------------- PTX helpers (sm_80-era only: safe at compute_103) ----------------
__device__ __forceinline__ uint32_t smem_u32(const void* p) {
    uint32_t a;
    asm("{ .reg .u64 t; cvta.to.shared.u64 t, %1; cvt.u32.u64 %0, t; }"
        : "=r"(a) : "l"(p));
    return a;
}

__device__ __forceinline__ void cp_async16(uint32_t saddr, const void* gaddr) {
    asm volatile("cp.async.cg.shared.global [%0], [%1], 16;"
                 :: "r"(saddr), "l"(gaddr) : "memory");
}

__device__ __forceinline__ void ldsm_x4(uint32_t (&r)[4], uint32_t addr) {
    asm volatile("ldmatrix.sync.aligned.m8n8.x4.shared.b16 {%0,%1,%2,%3}, [%4];"
                 : "=r"(r[0]), "=r"(r[1]), "=r"(r[2]), "=r"(r[3]) : "r"(addr));
}

// s8 MMA: D(s32) += A(s8,row) x B(s8,col), m16n8k32
__device__ __forceinline__ void mma_s8(int32_t (&d)[4], const uint32_t (&a)[4],
                                       const uint32_t* b) {
    asm volatile(
        "mma.sync.aligned.m16n8k32.row.col.s32.s8.s8.s32 "
        "{%0,%1,%2,%3}, {%4,%5,%6,%7}, {%8,%9}, {%0,%1,%2,%3};"
        : "+r"(d[0]), "+r"(d[1]), "+r"(d[2]), "+r"(d[3])
        : "r"(a[0]), "r"(a[1]), "r"(a[2]), "r"(a[3]), "r"(b[0]), "r"(b[1]));
}

// ---------------- Kernel 1: EMA scan (fp32 out) ----------------
// conv[t] = f*conv[t-1] + x[t];  x_mix[t] = xml*f^{t+1} + (1-f)*conv[t]
__global__ void __launch_bounds__(256) scan_kernel(const float* __restrict__ x,
                                                   const float* __restrict__ xml,
                                                   const float* __restrict__ fparam) {
    const int idx = blockIdx.x * blockDim.x + threadIdx.x;   // 0..16383 = b*D + d
    const int d = idx & (DIM - 1);
    const float f = 1.0f / (1.0f + expf(-fparam[d]));
    const float omf = 1.0f - f;
    float c = 0.0f;
    float m = xml[idx];
    const float* px = x + idx;
    float* po = g_xmix + idx;

    const int STRIDE = BATCH * DIM;   // 16384
    constexpr int U = 16;
    for (int t = 0; t < SEQ_L; t += U) {
        float xv[U];
#pragma unroll
        for (int u = 0; u < U; u++) xv[u] = px[(t + u) * STRIDE];
#pragma unroll
        for (int u = 0; u < U; u++) {
            c = fmaf(f, c, xv[u]);
            m *= f;
            po[(t + u) * STRIDE] = fmaf(omf, c, m);
        }
    }
}

// ---------------- Quantization: per-row int16 -> s8 hi/lo ----------------
__device__ __forceinline__ void quant4(const float4 v, float inv,
                                       uint32_t& hiw, uint32_t& low) {
    int q0 = __float2int_rn(v.x * inv);
    int q1 = __float2int_rn(v.y * inv);
    int q2 = __float2int_rn(v.z * inv);
    int q3 = __float2int_rn(v.w * inv);
    int h0 = (q0 + 128) >> 8, h1 = (q1 + 128) >> 8;
    int h2 = (q2 + 128) >> 8, h3 = (q3 + 128) >> 8;
    int l0 = q0 - (h0 << 8), l1 = q1 - (h1 << 8);
    int l2 = q2 - (h2 << 8), l3 = q3 - (h3 << 8);
    hiw = (h0 & 255) | ((h1 & 255) << 8) | ((h2 & 255) << 16) | ((h3 & 255) << 24);
    low = (l0 & 255) | ((l1 & 255) << 8) | ((l2 & 255) << 16) | ((l3 & 255) << 24);
}

// One block per row: read 2048 floats, row-max, quantize, write hi/lo planes.
__global__ void __launch_bounds__(256) rowquant_kernel(const float* __restrict__ src,
                                                       int8_t* __restrict__ dhi,
                                                       int8_t* __restrict__ dlo,
                                                       float* __restrict__ dscale) {
    const int row = blockIdx.x;
    const int tid = threadIdx.x;
    const float4* p = reinterpret_cast<const float4*>(src + (size_t)row * K_DIM);
    float4 v0 = p[tid];
    float4 v1 = p[tid + 256];
    float mx = fmaxf(fmaxf(fmaxf(fabsf(v0.x), fabsf(v0.y)), fmaxf(fabsf(v0.z), fabsf(v0.w))),
                     fmaxf(fmaxf(fabsf(v1.x), fabsf(v1.y)), fmaxf(fabsf(v1.z), fabsf(v1.w))));
#pragma unroll
    for (int o = 16; o > 0; o >>= 1)
        mx = fmaxf(mx, __shfl_xor_sync(0xFFFFFFFFu, mx, o));
    __shared__ float red[8];
    if ((tid & 31) == 0) red[tid >> 5] = mx;
    __syncthreads();
    float maxv = red[0];
#pragma unroll
    for (int i = 1; i < 8; i++) maxv = fmaxf(maxv, red[i]);

    const float inv = (maxv > 0.0f) ? (32639.0f / maxv) : 0.0f;
    uint32_t h0, l0, h1, l1;
    quant4(v0, inv, h0, l0);
    quant4(v1, inv, h1, l1);
    uint32_t* oh = reinterpret_cast<uint32_t*>(dhi + (size_t)row * K_DIM);
    uint32_t* ol = reinterpret_cast<uint32_t*>(dlo + (size_t)row * K_DIM);
    oh[tid] = h0; oh[tid + 256] = h1;
    ol[tid] = l0; ol[tid + 256] = l1;
    if (tid == 0) dscale[row] = maxv * (1.0f / 32639.0f);
}

// ---------------- Kernel 3: int8 emulated GEMM ----------------
// out[m,n] = s_x[m]*s_w[n]*(65536*sum(hi_x*hi_w) + 256*sum(hi_x*lo_w + lo_x*hi_w))
__device__ __forceinline__ void load_chunk(uint32_t sb, int tid, int m0, int n0, int ck) {
    const uint32_t tb = sb + (uint32_t)(ck & 1) * STAGE;
    const int koff = ck * KT;
    const int row = tid & 127;
    const bool hi = tid < 128;

    const int8_t* gA = hi ? g_xqh : g_xql;
    const uint32_t oA = hi ? OFF_AHI : OFF_ALO;
    const size_t ga = (size_t)(m0 + row) * K_DIM + koff;
    const uint32_t sa = tb + oA + (uint32_t)row * ROWB;
#pragma unroll
    for (int s = 0; s < 4; s++) cp_async16(sa + s * 16, gA + ga + s * 16);

    const int8_t* gB = hi ? g_wqh : g_wql;
    const uint32_t oB = hi ? OFF_BHI : OFF_BLO;
    const size_t gb = (size_t)(n0 + row) * K_DIM + koff;
    const uint32_t sB = tb + oB + (uint32_t)row * ROWB;
#pragma unroll
    for (int s = 0; s < 4; s++) cp_async16(sB + s * 16, gB + gb + s * 16);

    asm volatile("cp.async.commit_group;" ::: "memory");
}

__global__ void __launch_bounds__(256, 1) gemm_kernel(float* __restrict__ out) {
    extern __shared__ char smem[];
    const uint32_t sb = smem_u32(smem);
    const int tid = threadIdx.x;
    const int lid = tid & 31;
    const int wid = tid >> 5;
    const int wm = wid & 1;      // 2 warps along M (64 rows each)
    const int wn = wid >> 1;     // 4 warps along N (32 cols each)
    const int n0 = blockIdx.x * NT;   // x = n (L2 reuse of A across the wave)
    const int m0 = blockIdx.y * MT;

    int32_t acch[4][4][4];   // hi*hi
    int32_t accx[4][4][4];   // hi*lo + lo*hi (shared accumulator)
#pragma unroll
    for (int a = 0; a < 4; a++)
#pragma unroll
        for (int b = 0; b < 4; b++)
#pragma unroll
            for (int c = 0; c < 4; c++) { acch[a][b][c] = 0; accx[a][b][c] = 0; }

    // ldmatrix per-lane relative offsets.
    // A x4 (tile mt = 16 rows x k32): groups = rows(l&15), 16B col (l>>4): regs
    //   a0=rows0-7@k0-15, a1=rows8-15@k0-15, a2=rows0-7@k16-31, a3=rows8-15@k16-31.
    // B x4 (two n8 tiles x k32): groups 0-7: n0..7@k0-15; 8-15: @k16-31;
    //   16-23: n8..15@k0-15; 24-31: @k16-31 -> r0,r1 = tile n(0-7) b0,b1; r2,r3 = next.
    uint32_t relA[4], relB[2];
#pragma unroll
    for (int mt = 0; mt < 4; mt++)
        relA[mt] = (uint32_t)((wm * 64 + mt * 16 + (lid & 15)) * ROWB + (lid >> 4) * 16);
#pragma unroll
    for (int p = 0; p < 2; p++)
        relB[p] = (uint32_t)((wn * 32 + p * 16 + ((lid >> 4) << 3) + (lid & 7)) * ROWB
                             + ((lid >> 3) & 1) * 16);

    load_chunk(sb, tid, m0, n0, 0);

    for (int i = 0; i < NCHUNK; i++) {
        if (i + 1 < NCHUNK) {
            load_chunk(sb, tid, m0, n0, i + 1);
            asm volatile("cp.async.wait_group 1;" ::: "memory");
        } else {
            asm volatile("cp.async.wait_group 0;" ::: "memory");
        }
        __syncthreads();

        const uint32_t base = sb + (uint32_t)(i & 1) * STAGE;
#pragma unroll
        for (int ks = 0; ks < 2; ks++) {
            const uint32_t ko = (uint32_t)ks * 32;
            uint32_t ahi[4][4], alo[4][4], bhi[2][4], blo[2][4];
#pragma unroll
            for (int mt = 0; mt < 4; mt++) ldsm_x4(ahi[mt], base + OFF_AHI + relA[mt] + ko);
#pragma unroll
            for (int p = 0; p < 2; p++)   ldsm_x4(bhi[p], base + OFF_BHI + relB[p] + ko);
            // pass 1: hi*hi
#pragma unroll
            for (int mt = 0; mt < 4; mt++)
#pragma unroll
                for (int nt = 0; nt < 4; nt++)
                    mma_s8(acch[mt][nt], ahi[mt], &bhi[nt >> 1][(nt & 1) * 2]);
            // pass 2: hi_x * lo_w
#pragma unroll
            for (int p = 0; p < 2; p++)   ldsm_x4(blo[p], base + OFF_BLO + relB[p] + ko);
#pragma unroll
            for (int mt = 0; mt < 4; mt++)
#pragma unroll
                for (int nt = 0; nt < 4; nt++)
                    mma_s8(accx[mt][nt], ahi[mt], &blo[nt >> 1][(nt & 1) * 2]);
            // pass 3: lo_x * hi_w (same accumulator as pass 2)
#pragma unroll
            for (int mt = 0; mt < 4; mt++) ldsm_x4(alo[mt], base + OFF_ALO + relA[mt] + ko);
#pragma unroll
            for (int mt = 0; mt < 4; mt++)
#pragma unroll
                for (int nt = 0; nt < 4; nt++)
                    mma_s8(accx[mt][nt], alo[mt], &bhi[nt >> 1][(nt & 1) * 2]);
        }
        __syncthreads();
    }

    // Epilogue: dequant + store. Fragment: lane l -> row l/4 (+8), cols 2(l%4), +1.
    const int l4 = lid >> 2;
    const int l2 = (lid & 3) * 2;
#pragma unroll
    for (int mt = 0; mt < 4; mt++) {
        const int r0 = m0 + wm * 64 + mt * 16 + l4;
        const float sx0 = g_sx[r0];
        const float sx1 = g_sx[r0 + 8];
#pragma unroll
        for (int nt = 0; nt < 4; nt++) {
            const int cn = n0 + wn * 32 + nt * 8 + l2;
            const float2 sw = *reinterpret_cast<const float2*>(g_sw + cn);
            float v0 = 65536.0f * (float)acch[mt][nt][0] + 256.0f * (float)accx[mt][nt][0];
            float v1 = 65536.0f * (float)acch[mt][nt][1] + 256.0f * (float)accx[mt][nt][1];
            float v2 = 65536.0f * (float)acch[mt][nt][2] + 256.0f * (float)accx[mt][nt][2];
            float v3 = 65536.0f * (float)acch[mt][nt][3] + 256.0f * (float)accx[mt][nt][3];
            *reinterpret_cast<float2*>(out + (size_t)r0 * N_DIM + cn) =
                make_float2(sx0 * sw.x * v0, sx0 * sw.y * v1);
            *reinterpret_cast<float2*>(out + (size_t)(r0 + 8) * N_DIM + cn) =
                make_float2(sx1 * sw.x * v2, sx1 * sw.y * v3);
        }
    }
}

// ---------------- launch ----------------
extern "C" void kernel_launch(void* const* d_in, const int* in_sizes, int n_in,
                              void* d_out, int out_size) {
    const float *x = nullptr, *xml = nullptr, *fp = nullptr, *W = nullptr;
    for (int i = 0; i < n_in; i++) {
        int s = in_sizes[i];
        if (s == SEQ_L * BATCH * DIM)      x   = (const float*)d_in[i];
        else if (s == BATCH * DIM)         xml = (const float*)d_in[i];
        else if (s == DIM)                 fp  = (const float*)d_in[i];
        else if (s == DIM * DIM)           W   = (const float*)d_in[i];
    }

    cudaFuncSetAttribute(gemm_kernel, cudaFuncAttributeMaxDynamicSharedMemorySize, SMEM_TOTAL);

    int8_t *xqh, *xql, *wqh, *wql;
    float *sx, *sw, *xmix;
    cudaGetSymbolAddress((void**)&xmix, g_xmix);
    cudaGetSymbolAddress((void**)&xqh, g_xqh);
    cudaGetSymbolAddress((void**)&xql, g_xql);
    cudaGetSymbolAddress((void**)&wqh, g_wqh);
    cudaGetSymbolAddress((void**)&wql, g_wql);
    cudaGetSymbolAddress((void**)&sx, g_sx);
    cudaGetSymbolAddress((void**)&sw, g_sw);

    scan_kernel<<<(BATCH * DIM) / 256, 256>>>(x, xml, fp);
    rowquant_kernel<<<N_DIM, 256>>>(W, wqh, wql, sw);
    rowquant_kernel<<<M_ROWS, 256>>>(xmix, xqh, xql, sx);
    gemm_kernel<<<dim3(N_DIM / NT, M_ROWS / MT), 256, SMEM_TOTAL>>>((float*)d_out);
}

// round 6
// speedup vs baseline: 2.9862x; 2.9862x over previous
#include <cuda_runtime.h>
#include <cuda_fp16.h>
#include <cstdint>
#include <cstddef>

// Problem dims (fixed by the dataset)
#define SEQ_L 2048
#define BATCH 8
#define DIM   2048
#define M_ROWS (SEQ_L * BATCH)   // 16384
#define K_DIM  DIM
#define N_DIM  DIM
#define LANES  (BATCH * DIM)     // 16384

// Scan segmentation
#define NSEG 8
#define SEGLEN (SEQ_L / NSEG)    // 256

// GEMM tiling: CTA 128x128, 8 warps of 64x32, KT=32 (64B rows)
#define MT 128
#define NT 128
#define KT 32
#define NCHUNK (K_DIM / KT)      // 64
#define ROWB 80                  // 64B data + 16B pad (conflict-free ldmatrix)

#define OFF_AH 0
#define OFF_AL (128 * ROWB)          // 10240
#define OFF_BH (2 * 128 * ROWB)      // 20480
#define STAGE  (3 * 128 * ROWB)      // 30720
#define SMEM_TOTAL (2 * STAGE)       // 61440  -> 2 CTAs/SM

// Scratch (device globals — allocation-free rule)
__device__ __half g_ah[(size_t)M_ROWS * K_DIM];
__device__ __half g_al[(size_t)M_ROWS * K_DIM];
__device__ __half g_wh[(size_t)N_DIM * K_DIM];
__device__ float  g_segend[NSEG * LANES];

// ---------------- PTX helpers (sm_80-era only: safe at compute_103) ----------------
__device__ __forceinline__ uint32_t smem_u32(const void* p) {
    uint32_t a;
    asm("{ .reg .u64 t; cvta.to.shared.u64 t, %1; cvt.u32.u64 %0, t; }"
        : "=r"(a) : "l"(p));
    return a;
}

__device__ __forceinline__ void cp_async16(uint32_t saddr, const void* gaddr) {
    asm volatile("cp.async.cg.shared.global [%0], [%1], 16;"
                 :: "r"(saddr), "l"(gaddr) : "memory");
}

__device__ __forceinline__ void ldsm_x4(uint32_t (&r)[4], uint32_t addr) {
    asm volatile("ldmatrix.sync.aligned.m8n8.x4.shared.b16 {%0,%1,%2,%3}, [%4];"
                 : "=r"(r[0]), "=r"(r[1]), "=r"(r[2]), "=r"(r[3]) : "r"(addr));
}

__device__ __forceinline__ void mma_f16(float (&d)[4], const uint32_t (&a)[4],
                                        const uint32_t* b) {
    asm volatile(
        "mma.sync.aligned.m16n8k16.row.col.f32.f16.f16.f32 "
        "{%0,%1,%2,%3}, {%4,%5,%6,%7}, {%8,%9}, {%0,%1,%2,%3};"
        : "+f"(d[0]), "+f"(d[1]), "+f"(d[2]), "+f"(d[3])
        : "r"(a[0]), "r"(a[1]), "r"(a[2]), "r"(a[3]), "r"(b[0]), "r"(b[1]));
}

// ---------------- Scan phase A: per-segment local scan, save segment-end state ----
__global__ void __launch_bounds__(256) scanA_kernel(const float* __restrict__ x,
                                                    const float* __restrict__ fparam) {
    const int lane = blockIdx.x * blockDim.x + threadIdx.x;  // 0..16383
    const int seg = blockIdx.y;
    const float f = 1.0f / (1.0f + expf(-fparam[lane & (DIM - 1)]));
    const float* px = x + (size_t)seg * SEGLEN * LANES + lane;
    float c = 0.0f;
    constexpr int U = 16;
    for (int t = 0; t < SEGLEN; t += U) {
        float xv[U];
#pragma unroll
        for (int u = 0; u < U; u++) xv[u] = px[(t + u) * LANES];
#pragma unroll
        for (int u = 0; u < U; u++) c = fmaf(f, c, xv[u]);
    }
    g_segend[seg * LANES + lane] = c;
}

// ---------------- Scan phase B: propagate carry, rescan, emit fp16 hi/lo ----------
__global__ void __launch_bounds__(256) scanB_kernel(const float* __restrict__ x,
                                                    const float* __restrict__ xml,
                                                    const float* __restrict__ fparam) {
    const int lane = blockIdx.x * blockDim.x + threadIdx.x;
    const int seg = blockIdx.y;
    const float f = 1.0f / (1.0f + expf(-fparam[lane & (DIM - 1)]));
    const float omf = 1.0f - f;

    // f^SEGLEN by repeated squaring (SEGLEN = 256 = 2^8)
    float f256 = f;
#pragma unroll
    for (int i = 0; i < 8; i++) f256 *= f256;

    // G = global conv state entering this segment; fs = f^(seg*SEGLEN)
    float G = 0.0f, fs = 1.0f;
    for (int s = 0; s < seg; s++) {
        G = fmaf(f256, G, g_segend[s * LANES + lane]);
        fs *= f256;
    }

    float c = G;
    float m = xml[lane] * fs;
    const float* px = x + (size_t)seg * SEGLEN * LANES + lane;
    __half* ph = g_ah + (size_t)seg * SEGLEN * LANES + lane;
    __half* pl = g_al + (size_t)seg * SEGLEN * LANES + lane;

    constexpr int U = 16;
    for (int t = 0; t < SEGLEN; t += U) {
        float xv[U];
#pragma unroll
        for (int u = 0; u < U; u++) xv[u] = px[(t + u) * LANES];
#pragma unroll
        for (int u = 0; u < U; u++) {
            c = fmaf(f, c, xv[u]);
            m *= f;
            float xm = fmaf(omf, c, m);
            __half hi = __float2half_rn(xm);
            ph[(t + u) * LANES] = hi;
            pl[(t + u) * LANES] = __float2half_rn(xm - __half2float(hi));
        }
    }
}

// ---------------- W -> fp16 (hi only; dropped wl is the modeled error) ----------
__global__ void __launch_bounds__(256) whalf_kernel(const float* __restrict__ W) {
    const int i = blockIdx.x * blockDim.x + threadIdx.x;
    g_wh[i] = __float2half_rn(W[i]);
}

// ---------------- GEMM: fp16 2-pass (ah+al)*wh, fp32 accum ----------------
__device__ __forceinline__ void load_chunk(uint32_t sb, int tid, int m0, int n0, int ck) {
    const uint32_t tb = sb + (uint32_t)(ck & 1) * STAGE;
    const int koff = ck * KT;
    const int row = tid & 127;

    // job 1: A plane (tid<128 -> hi, else lo), row = tid&127
    {
        const __half* gA = (tid < 128) ? g_ah : g_al;
        const uint32_t oA = (tid < 128) ? OFF_AH : OFF_AL;
        const size_t ga = (size_t)(m0 + row) * K_DIM + koff;
        const uint32_t sa = tb + oA + (uint32_t)row * ROWB;
#pragma unroll
        for (int s = 0; s < 4; s++) cp_async16(sa + s * 16, gA + ga + s * 8);
    }
    // job 2: B hi, rows 0..127 handled by tid<128
    if (tid < 128) {
        const size_t gb = (size_t)(n0 + row) * K_DIM + koff;
        const uint32_t sB = tb + OFF_BH + (uint32_t)row * ROWB;
#pragma unroll
        for (int s = 0; s < 4; s++) cp_async16(sB + s * 16, g_wh + gb + s * 8);
    }
    asm volatile("cp.async.commit_group;" ::: "memory");
}

__global__ void __launch_bounds__(256, 2) gemm_kernel(float* __restrict__ out) {
    extern __shared__ char smem[];
    const uint32_t sb = smem_u32(smem);
    const int tid = threadIdx.x;
    const int lid = tid & 31;
    const int wid = tid >> 5;
    const int wm = wid & 1;      // 2 warps along M (64 rows each)
    const int wn = wid >> 1;     // 4 warps along N (32 cols each)
    const int n0 = blockIdx.x * NT;
    const int m0 = blockIdx.y * MT;

    float acc[4][4][4];
#pragma unroll
    for (int a = 0; a < 4; a++)
#pragma unroll
        for (int b = 0; b < 4; b++)
#pragma unroll
            for (int c = 0; c < 4; c++) acc[a][b][c] = 0.0f;

    // ldmatrix per-lane relative offsets (layouts validated in R4/R5 passes).
    uint32_t relA[4], relB[2];
#pragma unroll
    for (int mt = 0; mt < 4; mt++)
        relA[mt] = (uint32_t)((wm * 64 + mt * 16 + (lid & 15)) * ROWB + (lid >> 4) * 16);
#pragma unroll
    for (int p = 0; p < 2; p++)
        relB[p] = (uint32_t)((wn * 32 + p * 16 + ((lid >> 4) << 3) + (lid & 7)) * ROWB
                             + ((lid >> 3) & 1) * 16);

    load_chunk(sb, tid, m0, n0, 0);

    for (int i = 0; i < NCHUNK; i++) {
        if (i + 1 < NCHUNK) {
            load_chunk(sb, tid, m0, n0, i + 1);
            asm volatile("cp.async.wait_group 1;" ::: "memory");
        } else {
            asm volatile("cp.async.wait_group 0;" ::: "memory");
        }
        __syncthreads();

        const uint32_t base = sb + (uint32_t)(i & 1) * STAGE;
#pragma unroll
        for (int ks = 0; ks < 2; ks++) {
            const uint32_t ko = (uint32_t)ks * 32;
            uint32_t ahi[4][4], alo[4][4], bhi[2][4];
#pragma unroll
            for (int mt = 0; mt < 4; mt++) ldsm_x4(ahi[mt], base + OFF_AH + relA[mt] + ko);
#pragma unroll
            for (int p = 0; p < 2; p++)   ldsm_x4(bhi[p], base + OFF_BH + relB[p] + ko);
            // pass 1: ah * wh
#pragma unroll
            for (int mt = 0; mt < 4; mt++)
#pragma unroll
                for (int nt = 0; nt < 4; nt++)
                    mma_f16(acc[mt][nt], ahi[mt], &bhi[nt >> 1][(nt & 1) * 2]);
            // pass 2: al * wh (same accumulators — both weight 1)
#pragma unroll
            for (int mt = 0; mt < 4; mt++) ldsm_x4(alo[mt], base + OFF_AL + relA[mt] + ko);
#pragma unroll
            for (int mt = 0; mt < 4; mt++)
#pragma unroll
                for (int nt = 0; nt < 4; nt++)
                    mma_f16(acc[mt][nt], alo[mt], &bhi[nt >> 1][(nt & 1) * 2]);
        }
        __syncthreads();
    }

    // Epilogue: fragment lane l -> row l/4 (+8), cols 2(l%4), +1.
    const int l4 = lid >> 2;
    const int l2 = (lid & 3) * 2;
#pragma unroll
    for (int mt = 0; mt < 4; mt++) {
        const int r0 = m0 + wm * 64 + mt * 16 + l4;
#pragma unroll
        for (int nt = 0; nt < 4; nt++) {
            const int cn = n0 + wn * 32 + nt * 8 + l2;
            *reinterpret_cast<float2*>(out + (size_t)r0 * N_DIM + cn) =
                make_float2(acc[mt][nt][0], acc[mt][nt][1]);
            *reinterpret_cast<float2*>(out + (size_t)(r0 + 8) * N_DIM + cn) =
                make_float2(acc[mt][nt][2], acc[mt][nt][3]);
        }
    }
}

// ---------------- launch ----------------
extern "C" void kernel_launch(void* const* d_in, const int* in_sizes, int n_in,
                              void* d_out, int out_size) {
    const float *x = nullptr, *xml = nullptr, *fp = nullptr, *W = nullptr;
    for (int i = 0; i < n_in; i++) {
        int s = in_sizes[i];
        if (s == SEQ_L * BATCH * DIM)      x   = (const float*)d_in[i];
        else if (s == BATCH * DIM)         xml = (const float*)d_in[i];
        else if (s == DIM)                 fp  = (const float*)d_in[i];
        else if (s == DIM * DIM)           W   = (const float*)d_in[i];
    }

    cudaFuncSetAttribute(gemm_kernel, cudaFuncAttributeMaxDynamicSharedMemorySize, SMEM_TOTAL);

    scanA_kernel<<<dim3(LANES / 256, NSEG), 256>>>(x, fp);
    scanB_kernel<<<dim3(LANES / 256, NSEG), 256>>>(x, xml, fp);
    whalf_kernel<<<(N_DIM * K_DIM) / 256, 256>>>(W);
    gemm_kernel<<<dim3(N_DIM / NT, M_ROWS / MT), 256, SMEM_TOTAL>>>((float*)d_out);
}

// round 7
// speedup vs baseline: 4.6117x; 1.5443x over previous
#include <cuda_runtime.h>
#include <cuda_fp16.h>
#include <cstdint>
#include <cstddef>

// Problem dims (fixed by the dataset)
#define SEQ_L 2048
#define BATCH 8
#define DIM   2048
#define M_ROWS (SEQ_L * BATCH)   // 16384
#define K_DIM  DIM
#define N_DIM  DIM
#define LANES  (BATCH * DIM)     // 16384

// Scan segmentation
#define NSEG 8
#define SEGLEN (SEQ_L / NSEG)    // 256

// GEMM tiling: CTA 128(M) x 256(N), 8 warps of 64x64, KT=32 (64B rows)
#define MT 128
#define NT 256
#define KT 32
#define NCHUNK (K_DIM / KT)      // 64
#define ROWB 80                  // 64B data + 16B pad (conflict-free ldmatrix)

#define OFF_A 0
#define OFF_B (128 * ROWB)           // 10240
#define STAGE ((128 + 256) * ROWB)   // 30720
#define SMEM_TOTAL (2 * STAGE)       // 61440

// Scratch (device globals — allocation-free rule)
__device__ __half g_ah[(size_t)M_ROWS * K_DIM];
__device__ __half g_wh[(size_t)N_DIM * K_DIM];
__device__ float  g_segend[NSEG * LANES];

// ---------------- PTX helpers (sm_80-era only: safe at compute_103) ----------------
__device__ __forceinline__ uint32_t smem_u32(const void* p) {
    uint32_t a;
    asm("{ .reg .u64 t; cvta.to.shared.u64 t, %1; cvt.u32.u64 %0, t; }"
        : "=r"(a) : "l"(p));
    return a;
}

__device__ __forceinline__ void cp_async16(uint32_t saddr, const void* gaddr) {
    asm volatile("cp.async.cg.shared.global [%0], [%1], 16;"
                 :: "r"(saddr), "l"(gaddr) : "memory");
}

__device__ __forceinline__ void ldsm_x4(uint32_t (&r)[4], uint32_t addr) {
    asm volatile("ldmatrix.sync.aligned.m8n8.x4.shared.b16 {%0,%1,%2,%3}, [%4];"
                 : "=r"(r[0]), "=r"(r[1]), "=r"(r[2]), "=r"(r[3]) : "r"(addr));
}

__device__ __forceinline__ void mma_f16(float (&d)[4], const uint32_t (&a)[4],
                                        const uint32_t* b) {
    asm volatile(
        "mma.sync.aligned.m16n8k16.row.col.f32.f16.f16.f32 "
        "{%0,%1,%2,%3}, {%4,%5,%6,%7}, {%8,%9}, {%0,%1,%2,%3};"
        : "+f"(d[0]), "+f"(d[1]), "+f"(d[2]), "+f"(d[3])
        : "r"(a[0]), "r"(a[1]), "r"(a[2]), "r"(a[3]), "r"(b[0]), "r"(b[1]));
}

// ---------------- Scan phase A: per-segment local scan, save segment-end state ----
__global__ void __launch_bounds__(256) scanA_kernel(const float* __restrict__ x,
                                                    const float* __restrict__ fparam) {
    const int lane = blockIdx.x * blockDim.x + threadIdx.x;  // 0..16383
    const int seg = blockIdx.y;
    const float f = 1.0f / (1.0f + expf(-fparam[lane & (DIM - 1)]));
    const float* px = x + (size_t)seg * SEGLEN * LANES + lane;
    float c = 0.0f;
    constexpr int U = 16;
    for (int t = 0; t < SEGLEN; t += U) {
        float xv[U];
#pragma unroll
        for (int u = 0; u < U; u++) xv[u] = px[(t + u) * LANES];
#pragma unroll
        for (int u = 0; u < U; u++) c = fmaf(f, c, xv[u]);
    }
    g_segend[seg * LANES + lane] = c;
}

// ---------------- Scan phase B: propagate carry, rescan, emit fp16 ----------
__global__ void __launch_bounds__(256) scanB_kernel(const float* __restrict__ x,
                                                    const float* __restrict__ xml,
                                                    const float* __restrict__ fparam) {
    const int lane = blockIdx.x * blockDim.x + threadIdx.x;
    const int seg = blockIdx.y;
    const float f = 1.0f / (1.0f + expf(-fparam[lane & (DIM - 1)]));
    const float omf = 1.0f - f;

    // f^SEGLEN by repeated squaring (SEGLEN = 256 = 2^8)
    float f256 = f;
#pragma unroll
    for (int i = 0; i < 8; i++) f256 *= f256;

    // G = global conv state entering this segment; fs = f^(seg*SEGLEN)
    float G = 0.0f, fs = 1.0f;
    for (int s = 0; s < seg; s++) {
        G = fmaf(f256, G, g_segend[s * LANES + lane]);
        fs *= f256;
    }

    float c = G;
    float m = xml[lane] * fs;
    const float* px = x + (size_t)seg * SEGLEN * LANES + lane;
    __half* ph = g_ah + (size_t)seg * SEGLEN * LANES + lane;

    constexpr int U = 16;
    for (int t = 0; t < SEGLEN; t += U) {
        float xv[U];
#pragma unroll
        for (int u = 0; u < U; u++) xv[u] = px[(t + u) * LANES];
#pragma unroll
        for (int u = 0; u < U; u++) {
            c = fmaf(f, c, xv[u]);
            m *= f;
            ph[(t + u) * LANES] = __float2half_rn(fmaf(omf, c, m));
        }
    }
}

// ---------------- W -> fp16 ----------
__global__ void __launch_bounds__(256) whalf_kernel(const float* __restrict__ W) {
    const int i = blockIdx.x * blockDim.x + threadIdx.x;
    g_wh[i] = __float2half_rn(W[i]);
}

// ---------------- GEMM: 1-pass fp16, fp32 accum ----------------
__device__ __forceinline__ void load_chunk(uint32_t sb, int tid, int m0, int n0, int ck) {
    const uint32_t tb = sb + (uint32_t)(ck & 1) * STAGE;
    const int koff = ck * KT;
    if (tid < 128) {
        // A: 128 rows, 1 row per thread (4 x 16B)
        const size_t ga = (size_t)(m0 + tid) * K_DIM + koff;
        const uint32_t sa = tb + OFF_A + (uint32_t)tid * ROWB;
#pragma unroll
        for (int s = 0; s < 4; s++) cp_async16(sa + s * 16, g_ah + ga + s * 8);
    } else {
        // B: 256 rows, 2 rows per thread
        const int r0 = (tid - 128) * 2;
#pragma unroll
        for (int r = 0; r < 2; r++) {
            const size_t gb = (size_t)(n0 + r0 + r) * K_DIM + koff;
            const uint32_t sB = tb + OFF_B + (uint32_t)(r0 + r) * ROWB;
#pragma unroll
            for (int s = 0; s < 4; s++) cp_async16(sB + s * 16, g_wh + gb + s * 8);
        }
    }
    asm volatile("cp.async.commit_group;" ::: "memory");
}

__global__ void __launch_bounds__(256) gemm_kernel(float* __restrict__ out) {
    extern __shared__ char smem[];
    const uint32_t sb = smem_u32(smem);
    const int tid = threadIdx.x;
    const int lid = tid & 31;
    const int wid = tid >> 5;
    const int wm = wid & 1;      // 2 warps along M (64 rows each)
    const int wn = wid >> 1;     // 4 warps along N (64 cols each)
    const int n0 = blockIdx.x * NT;
    const int m0 = blockIdx.y * MT;

    float acc[4][8][4];
#pragma unroll
    for (int a = 0; a < 4; a++)
#pragma unroll
        for (int b = 0; b < 8; b++)
#pragma unroll
            for (int c = 0; c < 4; c++) acc[a][b][c] = 0.0f;

    // ldmatrix per-lane relative offsets (layouts validated in R4-R6 passes).
    // A x4: 16 rows x k16 per mt tile.  B x4: 16 n-rows x k16 per p tile
    //   (r0,r1 = first n8 tile's b-pair, r2,r3 = second).
    uint32_t relA[4], relB[4];
#pragma unroll
    for (int mt = 0; mt < 4; mt++)
        relA[mt] = (uint32_t)((wm * 64 + mt * 16 + (lid & 15)) * ROWB + (lid >> 4) * 16);
#pragma unroll
    for (int p = 0; p < 4; p++)
        relB[p] = (uint32_t)((wn * 64 + p * 16 + ((lid >> 4) << 3) + (lid & 7)) * ROWB
                             + ((lid >> 3) & 1) * 16);

    load_chunk(sb, tid, m0, n0, 0);

    for (int i = 0; i < NCHUNK; i++) {
        if (i + 1 < NCHUNK) {
            load_chunk(sb, tid, m0, n0, i + 1);
            asm volatile("cp.async.wait_group 1;" ::: "memory");
        } else {
            asm volatile("cp.async.wait_group 0;" ::: "memory");
        }
        __syncthreads();

        const uint32_t base = sb + (uint32_t)(i & 1) * STAGE;
#pragma unroll
        for (int ks = 0; ks < 2; ks++) {
            const uint32_t ko = (uint32_t)ks * 32;
            uint32_t afr[4][4], bfr[4][4];
#pragma unroll
            for (int mt = 0; mt < 4; mt++) ldsm_x4(afr[mt], base + OFF_A + relA[mt] + ko);
#pragma unroll
            for (int p = 0; p < 4; p++)   ldsm_x4(bfr[p], base + OFF_B + relB[p] + ko);
#pragma unroll
            for (int mt = 0; mt < 4; mt++)
#pragma unroll
                for (int nt = 0; nt < 8; nt++)
                    mma_f16(acc[mt][nt], afr[mt], &bfr[nt >> 1][(nt & 1) * 2]);
        }
        __syncthreads();
    }

    // Epilogue: fragment lane l -> row l/4 (+8), cols 2(l%4), +1.
    const int l4 = lid >> 2;
    const int l2 = (lid & 3) * 2;
#pragma unroll
    for (int mt = 0; mt < 4; mt++) {
        const int r0 = m0 + wm * 64 + mt * 16 + l4;
#pragma unroll
        for (int nt = 0; nt < 8; nt++) {
            const int cn = n0 + wn * 64 + nt * 8 + l2;
            *reinterpret_cast<float2*>(out + (size_t)r0 * N_DIM + cn) =
                make_float2(acc[mt][nt][0], acc[mt][nt][1]);
            *reinterpret_cast<float2*>(out + (size_t)(r0 + 8) * N_DIM + cn) =
                make_float2(acc[mt][nt][2], acc[mt][nt][3]);
        }
    }
}

// ---------------- launch ----------------
extern "C" void kernel_launch(void* const* d_in, const int* in_sizes, int n_in,
                              void* d_out, int out_size) {
    const float *x = nullptr, *xml = nullptr, *fp = nullptr, *W = nullptr;
    for (int i = 0; i < n_in; i++) {
        int s = in_sizes[i];
        if (s == SEQ_L * BATCH * DIM)      x   = (const float*)d_in[i];
        else if (s == BATCH * DIM)         xml = (const float*)d_in[i];
        else if (s == DIM)                 fp  = (const float*)d_in[i];
        else if (s == DIM * DIM)           W   = (const float*)d_in[i];
    }

    cudaFuncSetAttribute(gemm_kernel, cudaFuncAttributeMaxDynamicSharedMemorySize, SMEM_TOTAL);

    scanA_kernel<<<dim3(LANES / 256, NSEG), 256>>>(x, fp);
    scanB_kernel<<<dim3(LANES / 256, NSEG), 256>>>(x, xml, fp);
    whalf_kernel<<<(N_DIM * K_DIM) / 256, 256>>>(W);
    gemm_kernel<<<dim3(N_DIM / NT, M_ROWS / MT), 256, SMEM_TOTAL>>>((float*)d_out);
}